// round 1
// baseline (speedup 1.0000x reference)
#include <cuda_runtime.h>

#define BB   256
#define TT   2000
#define FIN  42
#define HH   24
#define G3   72
#define ROWS (BB * TT)

// 147.5 MB scratch for precomputed input-side gate preactivations xg[B,T,72]
__device__ float g_xg[(size_t)ROWS * G3];

__device__ __forceinline__ float fast_sigmoid(float x) {
    return __fdividef(1.0f, 1.0f + __expf(-x));
}
__device__ __forceinline__ float fast_tanh(float x) {
    return __fdividef(2.0f, 1.0f + __expf(-2.0f * x)) - 1.0f;
}

// ---------------------------------------------------------------------------
// Phase 1: xg[b,t,:] = W_ih @ tanh(lc1_w @ x[b,t,:] + lc1_b) + b_ih
// One thread per (b,t) row; x staged via shared (padded stride 43 -> no bank
// conflicts), weights in shared with uniform (broadcast) access.
// ---------------------------------------------------------------------------
__global__ __launch_bounds__(128) void vad_phase1(
    const float* __restrict__ x, const float* __restrict__ lc1_w,
    const float* __restrict__ lc1_b, const float* __restrict__ w_ih,
    const float* __restrict__ b_ih)
{
    __shared__ float s_w1[HH * FIN];
    __shared__ float s_b1[HH];
    __shared__ float s_wi[G3 * HH];
    __shared__ float s_bi[G3];
    __shared__ float s_x[128 * 43];

    int tid = threadIdx.x;
    for (int i = tid; i < HH * FIN; i += 128) s_w1[i] = lc1_w[i];
    for (int i = tid; i < G3 * HH; i += 128) s_wi[i] = w_ih[i];
    if (tid < HH) s_b1[tid] = lc1_b[tid];
    if (tid < G3) s_bi[tid] = b_ih[tid];

    size_t r0 = (size_t)blockIdx.x * 128;
    const float* xb = x + r0 * FIN;
    for (int i = tid; i < 128 * FIN; i += 128) {
        int row = i / FIN;
        int col = i - row * FIN;
        s_x[row * 43 + col] = xb[i];
    }
    __syncthreads();

    float xr[FIN];
#pragma unroll
    for (int f = 0; f < FIN; f++) xr[f] = s_x[tid * 43 + f];

    float a[HH];
#pragma unroll
    for (int h = 0; h < HH; h++) {
        float acc = s_b1[h];
#pragma unroll
        for (int f = 0; f < FIN; f++) acc = fmaf(xr[f], s_w1[h * FIN + f], acc);
        a[h] = fast_tanh(acc);
    }

    float4* out4 = reinterpret_cast<float4*>(g_xg + (r0 + tid) * G3);
#pragma unroll
    for (int q = 0; q < G3 / 4; q++) {
        int g = q * 4;
        float4 acc = make_float4(s_bi[g], s_bi[g + 1], s_bi[g + 2], s_bi[g + 3]);
#pragma unroll
        for (int h = 0; h < HH; h++) {
            float av = a[h];
            acc.x = fmaf(av, s_wi[(g + 0) * HH + h], acc.x);
            acc.y = fmaf(av, s_wi[(g + 1) * HH + h], acc.y);
            acc.z = fmaf(av, s_wi[(g + 2) * HH + h], acc.z);
            acc.w = fmaf(av, s_wi[(g + 3) * HH + h], acc.w);
        }
        out4[q] = acc;
    }
}

// ---------------------------------------------------------------------------
// Phase 2: GRU recurrence + lc2 head. One warp per batch row.
// h[i] lives in lane i (i<24); W_hh rows in registers; h broadcast via shfl.
// xg loads software-pipelined in chunks of 8 timesteps.
// ---------------------------------------------------------------------------
__global__ __launch_bounds__(32) void vad_phase2(
    const float* __restrict__ w_hh, const float* __restrict__ b_hh,
    const float* __restrict__ lc2_w, const float* __restrict__ lc2_b,
    float* __restrict__ out)
{
    int lane = threadIdx.x;
    int b = blockIdx.x;
    int i = (lane < HH) ? lane : 0;  // clamp upper lanes (no OOB, values unused)

    float wr[HH], wz[HH], wn[HH];
#pragma unroll
    for (int j = 0; j < HH; j++) {
        wr[j] = w_hh[(0 * HH + i) * HH + j];
        wz[j] = w_hh[(1 * HH + i) * HH + j];
        wn[j] = w_hh[(2 * HH + i) * HH + j];
    }
    float bhr = b_hh[0 * HH + i];
    float bhz = b_hh[1 * HH + i];
    float bhn = b_hh[2 * HH + i];
    float l2w = (lane < HH) ? lc2_w[i] : 0.0f;
    float l2b = lc2_b[0];

    const float* xgp = g_xg + (size_t)b * TT * G3;
    float* outp = out + (size_t)b * TT;

    float h = 0.0f;
    const int U = 8;  // TT % U == 0
    float cr[U], cz[U], cn[U];
#pragma unroll
    for (int u = 0; u < U; u++) {
        cr[u] = xgp[u * G3 + 0 * HH + i];
        cz[u] = xgp[u * G3 + 1 * HH + i];
        cn[u] = xgp[u * G3 + 2 * HH + i];
    }

    for (int t0 = 0; t0 < TT; t0 += U) {
        // Prefetch next chunk while computing current (hides DRAM latency).
        float nr[U], nz[U], nn[U];
        bool more = (t0 + U) < TT;
        const float* np = xgp + (size_t)(t0 + U) * G3;
#pragma unroll
        for (int u = 0; u < U; u++) {
            nr[u] = more ? np[u * G3 + 0 * HH + i] : 0.0f;
            nz[u] = more ? np[u * G3 + 1 * HH + i] : 0.0f;
            nn[u] = more ? np[u * G3 + 2 * HH + i] : 0.0f;
        }

#pragma unroll
        for (int u = 0; u < U; u++) {
            float hr = bhr, hz = bhz, hn = bhn;
#pragma unroll
            for (int j = 0; j < HH; j++) {
                float hj = __shfl_sync(0xffffffffu, h, j);
                hr = fmaf(wr[j], hj, hr);
                hz = fmaf(wz[j], hj, hz);
                hn = fmaf(wn[j], hj, hn);
            }
            float r = fast_sigmoid(cr[u] + hr);
            float z = fast_sigmoid(cz[u] + hz);
            float n = fast_tanh(fmaf(r, hn, cn[u]));
            h = fmaf(z, h - n, n);  // (1-z)*n + z*h

            // lc2 head: warp-reduce l2w*h over lanes (upper lanes contribute 0)
            float v = l2w * h;
#pragma unroll
            for (int off = 16; off > 0; off >>= 1)
                v += __shfl_xor_sync(0xffffffffu, v, off);
            if (lane == 0) outp[t0 + u] = fast_sigmoid(v + l2b);
        }

#pragma unroll
        for (int u = 0; u < U; u++) { cr[u] = nr[u]; cz[u] = nz[u]; cn[u] = nn[u]; }
    }
}

extern "C" void kernel_launch(void* const* d_in, const int* in_sizes, int n_in,
                              void* d_out, int out_size) {
    const float* x     = (const float*)d_in[0];
    const float* lc1_w = (const float*)d_in[1];
    const float* lc1_b = (const float*)d_in[2];
    const float* w_ih  = (const float*)d_in[3];
    const float* w_hh  = (const float*)d_in[4];
    const float* b_ih  = (const float*)d_in[5];
    const float* b_hh  = (const float*)d_in[6];
    const float* lc2_w = (const float*)d_in[7];
    const float* lc2_b = (const float*)d_in[8];
    float* out = (float*)d_out;

    vad_phase1<<<ROWS / 128, 128>>>(x, lc1_w, lc1_b, w_ih, b_ih);
    vad_phase2<<<BB, 32>>>(w_hh, b_hh, lc2_w, lc2_b, out);
}

// round 2
// speedup vs baseline: 1.2360x; 1.2360x over previous
#include <cuda_runtime.h>

typedef unsigned long long ull;

#define BB   256
#define TT   2000
#define FIN  42
#define FINP 44
#define HH   24
#define G3   72
#define ROWS (BB * TT)

// 147.5 MB scratch for precomputed input-side gate preactivations xg[B,T,72]
__device__ float g_xg[(size_t)ROWS * G3];

__device__ __forceinline__ float tanh_a(float x) {
    float y; asm("tanh.approx.f32 %0, %1;" : "=f"(y) : "f"(x)); return y;
}
__device__ __forceinline__ float sigm_a(float x) {
    return fmaf(tanh_a(0.5f * x), 0.5f, 0.5f);
}
__device__ __forceinline__ ull fma2(ull a, ull b, ull c) {
    ull d; asm("fma.rn.f32x2 %0, %1, %2, %3;" : "=l"(d) : "l"(a), "l"(b), "l"(c)); return d;
}
__device__ __forceinline__ ull pack2(float lo, float hi) {
    ull d; asm("mov.b64 %0, {%1, %2};" : "=l"(d) : "f"(lo), "f"(hi)); return d;
}
__device__ __forceinline__ float2 unpack2(ull v) {
    float2 r; asm("mov.b64 {%0, %1}, %2;" : "=f"(r.x), "=f"(r.y) : "l"(v)); return r;
}

// ---------------------------------------------------------------------------
// Phase 1: xg[b,t,:] = W_ih @ tanh(lc1_w @ x[b,t,:] + lc1_b) + b_ih
// One thread per (b,t) row. Weights via vectorized shared loads; all dot
// products in packed f32x2 FMAs (halves FMA issue count).
// ---------------------------------------------------------------------------
__global__ __launch_bounds__(128) void vad_phase1(
    const float* __restrict__ x, const float* __restrict__ lc1_w,
    const float* __restrict__ lc1_b, const float* __restrict__ w_ih,
    const float* __restrict__ b_ih)
{
    __shared__ __align__(16) float s_w1[HH * FINP];   // lc1_w padded to stride 44
    __shared__ float s_b1[HH];
    __shared__ __align__(16) ull s_wi2[G3 * 12];      // w_ih rows as 12 packed pairs
    __shared__ float s_bi[G3];
    __shared__ __align__(16) float s_x[128 * FINP];   // x rows padded to stride 44

    int tid = threadIdx.x;
    for (int i = tid; i < HH * FINP; i += 128) {
        int h = i / FINP, f = i - h * FINP;
        s_w1[i] = (f < FIN) ? lc1_w[h * FIN + f] : 0.0f;
    }
    const ull* wi8 = (const ull*)w_ih;                // 72x24 floats = 864 ull
    for (int i = tid; i < G3 * 12; i += 128) s_wi2[i] = wi8[i];
    if (tid < HH) s_b1[tid] = lc1_b[tid];
    if (tid < G3) s_bi[tid] = b_ih[tid];

    size_t r0 = (size_t)blockIdx.x * 128;
    const float* xb = x + r0 * FIN;
    for (int i = tid; i < 128 * FINP; i += 128) {
        int row = i / FINP, col = i - row * FINP;
        s_x[i] = (col < FIN) ? xb[row * FIN + col] : 0.0f;
    }
    __syncthreads();

    // x row -> 22 packed pairs (stride-44 float4 LDS is bank-conflict-free)
    ull xp[22];
    {
        const float4* xv = (const float4*)&s_x[tid * FINP];
#pragma unroll
        for (int q = 0; q < 11; q++) {
            float4 t = xv[q];
            xp[2 * q]     = pack2(t.x, t.y);
            xp[2 * q + 1] = pack2(t.z, t.w);
        }
    }

    // lc1 + tanh
    float a[HH];
#pragma unroll
    for (int h = 0; h < HH; h++) {
        const ulonglong2* wv = (const ulonglong2*)&s_w1[h * FINP];
        ull p = pack2(s_b1[h], 0.0f), q = 0ULL;
#pragma unroll
        for (int m = 0; m < 11; m++) {
            ulonglong2 w = wv[m];
            p = fma2(w.x, xp[2 * m], p);
            q = fma2(w.y, xp[2 * m + 1], q);
        }
        float2 fp = unpack2(p), fq = unpack2(q);
        a[h] = tanh_a((fp.x + fp.y) + (fq.x + fq.y));
    }

    ull a2[12];
#pragma unroll
    for (int k = 0; k < 12; k++) a2[k] = pack2(a[2 * k], a[2 * k + 1]);

    // W_ih @ a + b_ih, 4 outputs buffered per STG.128
    float4* out4 = (float4*)(g_xg + (r0 + tid) * G3);
#pragma unroll
    for (int g4 = 0; g4 < 18; g4++) {
        float o[4];
#pragma unroll
        for (int s = 0; s < 4; s++) {
            int g = g4 * 4 + s;
            const ulonglong2* w2 = (const ulonglong2*)&s_wi2[g * 12];
            ull p = pack2(s_bi[g], 0.0f), q = 0ULL;
#pragma unroll
            for (int m = 0; m < 6; m++) {
                ulonglong2 w = w2[m];
                p = fma2(w.x, a2[2 * m], p);
                q = fma2(w.y, a2[2 * m + 1], q);
            }
            float2 fp = unpack2(p), fq = unpack2(q);
            o[s] = (fp.x + fp.y) + (fq.x + fq.y);
        }
        out4[g4] = make_float4(o[0], o[1], o[2], o[3]);
    }
}

// ---------------------------------------------------------------------------
// Phase 2: GRU recurrence + lc2 head. One warp per batch row.
// h[i] in lane i; broadcast via double-buffered shared (1 STS + 6 LDS.128
// instead of 24 SHFLs); W_hh matvec in packed f32x2 FMAs.
// ---------------------------------------------------------------------------
__global__ __launch_bounds__(32) void vad_phase2(
    const float* __restrict__ w_hh, const float* __restrict__ b_hh,
    const float* __restrict__ lc2_w, const float* __restrict__ lc2_b,
    float* __restrict__ out)
{
    __shared__ __align__(16) float s_h[2][32];
    int lane = threadIdx.x;
    int b = blockIdx.x;
    int i = (lane < HH) ? lane : 0;   // clamp upper lanes

    const ull* w8 = (const ull*)w_hh;  // 24 floats/row = 12 packed pairs
    ull wr2[12], wz2[12], wn2[12];
#pragma unroll
    for (int k = 0; k < 12; k++) {
        wr2[k] = w8[(0 * HH + i) * 12 + k];
        wz2[k] = w8[(1 * HH + i) * 12 + k];
        wn2[k] = w8[(2 * HH + i) * 12 + k];
    }
    ull br2 = pack2(b_hh[0 * HH + i], 0.0f);
    ull bz2 = pack2(b_hh[1 * HH + i], 0.0f);
    ull bn2 = pack2(b_hh[2 * HH + i], 0.0f);
    float l2w = (lane < HH) ? lc2_w[i] : 0.0f;
    float l2b = lc2_b[0];

    const float* xgp = g_xg + (size_t)b * TT * G3;
    float* outp = out + (size_t)b * TT;

    float h = 0.0f;
    const int U = 4;   // TT % U == 0
    float cr[U], cz[U], cn[U];
#pragma unroll
    for (int u = 0; u < U; u++) {
        cr[u] = xgp[u * G3 + 0 * HH + i];
        cz[u] = xgp[u * G3 + 1 * HH + i];
        cn[u] = xgp[u * G3 + 2 * HH + i];
    }

    for (int t0 = 0; t0 < TT; t0 += U) {
        // prefetch next chunk (hides DRAM latency behind ~U serial steps)
        float nr[U], nz[U], nn[U];
        bool more = (t0 + U) < TT;
        const float* np = xgp + (size_t)(t0 + U) * G3;
#pragma unroll
        for (int u = 0; u < U; u++) {
            nr[u] = more ? np[u * G3 + 0 * HH + i] : 0.0f;
            nz[u] = more ? np[u * G3 + 1 * HH + i] : 0.0f;
            nn[u] = more ? np[u * G3 + 2 * HH + i] : 0.0f;
        }

#pragma unroll
        for (int u = 0; u < U; u++) {
            int pb = u & 1;                    // double buffer: no WAR sync needed
            s_h[pb][lane] = h;
            __syncwarp();
            ull h2[12];
            {
                const ulonglong2* sh2 = (const ulonglong2*)&s_h[pb][0];
#pragma unroll
                for (int k = 0; k < 6; k++) {
                    ulonglong2 t = sh2[k];
                    h2[2 * k] = t.x; h2[2 * k + 1] = t.y;
                }
            }
            ull ra = br2, rb = 0ULL, za = bz2, zb = 0ULL, na = bn2, nb = 0ULL;
#pragma unroll
            for (int m = 0; m < 6; m++) {
                ra = fma2(wr2[2 * m], h2[2 * m], ra);
                rb = fma2(wr2[2 * m + 1], h2[2 * m + 1], rb);
                za = fma2(wz2[2 * m], h2[2 * m], za);
                zb = fma2(wz2[2 * m + 1], h2[2 * m + 1], zb);
                na = fma2(wn2[2 * m], h2[2 * m], na);
                nb = fma2(wn2[2 * m + 1], h2[2 * m + 1], nb);
            }
            float2 f1 = unpack2(ra), f2 = unpack2(rb);
            float hr = (f1.x + f1.y) + (f2.x + f2.y);
            f1 = unpack2(za); f2 = unpack2(zb);
            float hz = (f1.x + f1.y) + (f2.x + f2.y);
            f1 = unpack2(na); f2 = unpack2(nb);
            float hn = (f1.x + f1.y) + (f2.x + f2.y);

            float r = sigm_a(cr[u] + hr);
            float z = sigm_a(cz[u] + hz);
            float n = tanh_a(fmaf(r, hn, cn[u]));
            h = fmaf(z, h - n, n);             // (1-z)*n + z*h

            float v = l2w * h;
#pragma unroll
            for (int off = 16; off > 0; off >>= 1)
                v += __shfl_xor_sync(0xffffffffu, v, off);
            if (lane == 0) outp[t0 + u] = sigm_a(v + l2b);
        }

#pragma unroll
        for (int u = 0; u < U; u++) { cr[u] = nr[u]; cz[u] = nz[u]; cn[u] = nn[u]; }
    }
}

extern "C" void kernel_launch(void* const* d_in, const int* in_sizes, int n_in,
                              void* d_out, int out_size) {
    const float* x     = (const float*)d_in[0];
    const float* lc1_w = (const float*)d_in[1];
    const float* lc1_b = (const float*)d_in[2];
    const float* w_ih  = (const float*)d_in[3];
    const float* w_hh  = (const float*)d_in[4];
    const float* b_ih  = (const float*)d_in[5];
    const float* b_hh  = (const float*)d_in[6];
    const float* lc2_w = (const float*)d_in[7];
    const float* lc2_b = (const float*)d_in[8];
    float* out = (float*)d_out;

    vad_phase1<<<ROWS / 128, 128>>>(x, lc1_w, lc1_b, w_ih, b_ih);
    vad_phase2<<<BB, 32>>>(w_hh, b_hh, lc2_w, lc2_b, out);
}

// round 4
// speedup vs baseline: 1.3623x; 1.1022x over previous
#include <cuda_runtime.h>

typedef unsigned long long ull;

#define BB   256
#define TT   2000
#define FIN  42
#define FINP 44
#define HH   24
#define G3   72
#define ROWS (BB * TT)

// scratch: xg[B,T,72] gate preactivations (147.5 MB), h[B,T,24] states (49 MB)
__device__ float g_xg[(size_t)ROWS * G3];
__device__ float g_h[(size_t)ROWS * HH];

__device__ __forceinline__ float tanh_a(float x) {
    float y; asm("tanh.approx.f32 %0, %1;" : "=f"(y) : "f"(x)); return y;
}
__device__ __forceinline__ ull fma2(ull a, ull b, ull c) {
    ull d; asm("fma.rn.f32x2 %0, %1, %2, %3;" : "=l"(d) : "l"(a), "l"(b), "l"(c)); return d;
}
__device__ __forceinline__ ull add2(ull a, ull b) {
    ull d; asm("add.rn.f32x2 %0, %1, %2;" : "=l"(d) : "l"(a), "l"(b)); return d;
}
__device__ __forceinline__ ull pack2(float lo, float hi) {
    ull d; asm("mov.b64 %0, {%1, %2};" : "=l"(d) : "f"(lo), "f"(hi)); return d;
}
__device__ __forceinline__ float2 unpack2(ull v) {
    float2 r; asm("mov.b64 {%0, %1}, %2;" : "=f"(r.x), "=f"(r.y) : "l"(v)); return r;
}
__device__ __forceinline__ float hsum2(ull v) {
    float2 r = unpack2(v); return r.x + r.y;
}

// ---------------------------------------------------------------------------
// Phase 1: xg[b,t,:] = W_ih @ tanh(lc1_w @ x[b,t,:] + lc1_b) + b_ih
// 2 rows per thread (weight LDS amortized). x rows loaded directly from
// global as 21 LDG.64 each (168-byte rows are 8B-aligned; coalesced across
// the warp) — no x staging in shared, so smem = weights only (~11.6 KB).
// ---------------------------------------------------------------------------
__global__ __launch_bounds__(128) void vad_phase1(
    const float* __restrict__ x, const float* __restrict__ lc1_w,
    const float* __restrict__ lc1_b, const float* __restrict__ w_ih,
    const float* __restrict__ b_ih)
{
    __shared__ __align__(16) float s_w1[HH * FINP];   // lc1_w padded stride 44
    __shared__ float s_b1[HH];
    __shared__ __align__(16) ull s_wi2[G3 * 12];      // w_ih rows, 12 pairs each
    __shared__ float s_bi[G3];

    int tid = threadIdx.x;
    for (int i = tid; i < HH * FINP; i += 128) {
        int h = i / FINP, f = i - h * FINP;
        s_w1[i] = (f < FIN) ? lc1_w[h * FIN + f] : 0.0f;
    }
    const ull* wi8 = (const ull*)w_ih;
    for (int i = tid; i < G3 * 12; i += 128) s_wi2[i] = wi8[i];
    if (tid < HH) s_b1[tid] = lc1_b[tid];
    if (tid < G3) s_bi[tid] = b_ih[tid];
    __syncthreads();

    size_t r0 = (size_t)blockIdx.x * 256;
    // rows for this thread: A = r0+tid, B = r0+128+tid. 168 B/row -> 8B aligned.
    const ull* xA = (const ull*)(x + (r0 + tid) * FIN);
    const ull* xB = (const ull*)(x + (r0 + 128 + tid) * FIN);

    ull xpA[22], xpB[22];
#pragma unroll
    for (int q = 0; q < 21; q++) { xpA[q] = xA[q]; xpB[q] = xB[q]; }
    xpA[21] = 0ULL; xpB[21] = 0ULL;   // pad to match stride-44 weights

    // lc1 + tanh for both rows; weight row loaded once
    float aA[HH], aB[HH];
#pragma unroll
    for (int h = 0; h < HH; h++) {
        const ulonglong2* wv = (const ulonglong2*)&s_w1[h * FINP];
        float b = s_b1[h];
        ull pA = pack2(b, 0.0f), qA = 0ULL, pB = pack2(b, 0.0f), qB = 0ULL;
#pragma unroll
        for (int m = 0; m < 11; m++) {
            ulonglong2 w = wv[m];
            pA = fma2(w.x, xpA[2 * m], pA);
            qA = fma2(w.y, xpA[2 * m + 1], qA);
            pB = fma2(w.x, xpB[2 * m], pB);
            qB = fma2(w.y, xpB[2 * m + 1], qB);
        }
        aA[h] = tanh_a(hsum2(add2(pA, qA)));
        aB[h] = tanh_a(hsum2(add2(pB, qB)));
    }

    ull a2A[12], a2B[12];
#pragma unroll
    for (int k = 0; k < 12; k++) {
        a2A[k] = pack2(aA[2 * k], aA[2 * k + 1]);
        a2B[k] = pack2(aB[2 * k], aB[2 * k + 1]);
    }

    // W_ih @ a + b_ih for both rows; weight row loaded once
    float4* outA = (float4*)(g_xg + (r0 + tid) * G3);
    float4* outB = (float4*)(g_xg + (r0 + 128 + tid) * G3);
#pragma unroll
    for (int g4 = 0; g4 < 18; g4++) {
        float oA[4], oB[4];
#pragma unroll
        for (int s = 0; s < 4; s++) {
            int g = g4 * 4 + s;
            const ulonglong2* w2 = (const ulonglong2*)&s_wi2[g * 12];
            float b = s_bi[g];
            ull pA = pack2(b, 0.0f), qA = 0ULL, pB = pack2(b, 0.0f), qB = 0ULL;
#pragma unroll
            for (int m = 0; m < 6; m++) {
                ulonglong2 w = w2[m];
                pA = fma2(w.x, a2A[2 * m], pA);
                qA = fma2(w.y, a2A[2 * m + 1], qA);
                pB = fma2(w.x, a2B[2 * m], pB);
                qB = fma2(w.y, a2B[2 * m + 1], qB);
            }
            oA[s] = hsum2(add2(pA, qA));
            oB[s] = hsum2(add2(pB, qB));
        }
        outA[g4] = make_float4(oA[0], oA[1], oA[2], oA[3]);
        outB[g4] = make_float4(oB[0], oB[1], oB[2], oB[3]);
    }
}

// ---------------------------------------------------------------------------
// Phase 2: GRU recurrence only. One warp per batch row; h[i] in lane i.
// Head hoisted out (h stored to g_h). Biases + input preactivations folded
// into accumulator init during the (off-critical-path) prefetch; W_r/W_z and
// their preactivations pre-scaled by 0.5 so sigmoid = fma(tanh, 0.5, 0.5).
// ---------------------------------------------------------------------------
__global__ __launch_bounds__(32) void vad_phase2(
    const float* __restrict__ w_hh, const float* __restrict__ b_hh)
{
    __shared__ __align__(16) float s_h[2][32];
    int lane = threadIdx.x;
    int b = blockIdx.x;
    int i = (lane < HH) ? lane : 0;

    const ull* w8 = (const ull*)w_hh;
    ull wr2[12], wz2[12], wn2[12];
#pragma unroll
    for (int k = 0; k < 12; k++) {
        float2 r = unpack2(w8[(0 * HH + i) * 12 + k]);
        wr2[k] = pack2(0.5f * r.x, 0.5f * r.y);          // pre-scaled 0.5
        float2 z = unpack2(w8[(1 * HH + i) * 12 + k]);
        wz2[k] = pack2(0.5f * z.x, 0.5f * z.y);
        wn2[k] = w8[(2 * HH + i) * 12 + k];
    }
    float bhr_h = 0.5f * b_hh[0 * HH + i];
    float bhz_h = 0.5f * b_hh[1 * HH + i];
    ull  bn2   = pack2(b_hh[2 * HH + i], 0.0f);

    const float* xgp = g_xg + (size_t)b * TT * G3;
    float* hp = g_h + (size_t)b * TT * HH;

    float h = 0.0f;
    const int U = 4;   // TT % U == 0
    float cr[U], cz[U], cn[U];
#pragma unroll
    for (int u = 0; u < U; u++) {
        cr[u] = fmaf(0.5f, xgp[u * G3 + 0 * HH + i], bhr_h);
        cz[u] = fmaf(0.5f, xgp[u * G3 + 1 * HH + i], bhz_h);
        cn[u] = xgp[u * G3 + 2 * HH + i];
    }

    for (int t0 = 0; t0 < TT; t0 += U) {
        // prefetch + bias folding for next chunk (off the serial chain)
        float nr[U], nz[U], nn[U];
        bool more = (t0 + U) < TT;
        const float* np = xgp + (size_t)(t0 + U) * G3;
#pragma unroll
        for (int u = 0; u < U; u++) {
            float lr = more ? np[u * G3 + 0 * HH + i] : 0.0f;
            float lz = more ? np[u * G3 + 1 * HH + i] : 0.0f;
            nn[u]    = more ? np[u * G3 + 2 * HH + i] : 0.0f;
            nr[u] = fmaf(0.5f, lr, bhr_h);
            nz[u] = fmaf(0.5f, lz, bhz_h);
        }

#pragma unroll
        for (int u = 0; u < U; u++) {
            int pb = u & 1;
            s_h[pb][lane] = h;
            __syncwarp();
            ull h2[12];
            {
                const ulonglong2* sh2 = (const ulonglong2*)&s_h[pb][0];
#pragma unroll
                for (int k = 0; k < 6; k++) {
                    ulonglong2 t = sh2[k];
                    h2[2 * k] = t.x; h2[2 * k + 1] = t.y;
                }
            }
            ull ra = pack2(cr[u], 0.0f), rb = 0ULL;
            ull za = pack2(cz[u], 0.0f), zb = 0ULL;
            ull na = bn2, nb = 0ULL;
#pragma unroll
            for (int m = 0; m < 6; m++) {
                ra = fma2(wr2[2 * m], h2[2 * m], ra);
                rb = fma2(wr2[2 * m + 1], h2[2 * m + 1], rb);
                za = fma2(wz2[2 * m], h2[2 * m], za);
                zb = fma2(wz2[2 * m + 1], h2[2 * m + 1], zb);
                na = fma2(wn2[2 * m], h2[2 * m], na);
                nb = fma2(wn2[2 * m + 1], h2[2 * m + 1], nb);
            }
            float hr = hsum2(add2(ra, rb));
            float hz = hsum2(add2(za, zb));
            float hn = hsum2(add2(na, nb));

            float r = fmaf(tanh_a(hr), 0.5f, 0.5f);
            float z = fmaf(tanh_a(hz), 0.5f, 0.5f);
            float n = tanh_a(fmaf(r, hn, cn[u]));
            h = fmaf(z, h - n, n);

            if (lane < HH) hp[(t0 + u) * HH + lane] = h;
        }

#pragma unroll
        for (int u = 0; u < U; u++) { cr[u] = nr[u]; cz[u] = nz[u]; cn[u] = nn[u]; }
    }
}

// ---------------------------------------------------------------------------
// Phase 3: out[b,t] = sigmoid(lc2_w . h[b,t,:] + lc2_b). One thread per row.
// ---------------------------------------------------------------------------
__global__ __launch_bounds__(256) void vad_phase3(
    const float* __restrict__ lc2_w, const float* __restrict__ lc2_b,
    float* __restrict__ out)
{
    size_t idx = (size_t)blockIdx.x * 256 + threadIdx.x;
    const float4* hv = (const float4*)(g_h + idx * HH);
    const float4* wv = (const float4*)lc2_w;

    ull acc = pack2(0.5f * lc2_b[0], 0.0f);
#pragma unroll
    for (int q = 0; q < 6; q++) {
        float4 hq = hv[q];
        float4 wq = __ldg(&wv[q]);
        acc = fma2(pack2(hq.x, hq.y), pack2(0.5f * wq.x, 0.5f * wq.y), acc);
        acc = fma2(pack2(hq.z, hq.w), pack2(0.5f * wq.z, 0.5f * wq.w), acc);
    }
    out[idx] = fmaf(tanh_a(hsum2(acc)), 0.5f, 0.5f);
}

extern "C" void kernel_launch(void* const* d_in, const int* in_sizes, int n_in,
                              void* d_out, int out_size) {
    const float* x     = (const float*)d_in[0];
    const float* lc1_w = (const float*)d_in[1];
    const float* lc1_b = (const float*)d_in[2];
    const float* w_ih  = (const float*)d_in[3];
    const float* w_hh  = (const float*)d_in[4];
    const float* b_ih  = (const float*)d_in[5];
    const float* b_hh  = (const float*)d_in[6];
    const float* lc2_w = (const float*)d_in[7];
    const float* lc2_b = (const float*)d_in[8];
    float* out = (float*)d_out;

    vad_phase1<<<ROWS / 256, 128>>>(x, lc1_w, lc1_b, w_ih, b_ih);
    vad_phase2<<<BB, 32>>>(w_hh, b_hh);
    vad_phase3<<<ROWS / 256, 256>>>(lc2_w, lc2_b, out);
}

// round 5
// speedup vs baseline: 1.7590x; 1.2912x over previous
#include <cuda_runtime.h>

typedef unsigned long long ull;

#define BB   256
#define TT   2000
#define FIN  42
#define FINP 44
#define HH   24
#define G3   72
#define ROWS (BB * TT)

// scratch: xg2[row][i][4] = (cr, cz, cn, 0) pre-folded gate preacts (196.6 MB)
//          h[B,T,24] states (49 MB)
__device__ float g_xg2[(size_t)ROWS * HH * 4];
__device__ float g_h[(size_t)ROWS * HH];

__device__ __forceinline__ float tanh_a(float x) {
    float y; asm("tanh.approx.f32 %0, %1;" : "=f"(y) : "f"(x)); return y;
}
__device__ __forceinline__ ull fma2(ull a, ull b, ull c) {
    ull d; asm("fma.rn.f32x2 %0, %1, %2, %3;" : "=l"(d) : "l"(a), "l"(b), "l"(c)); return d;
}
__device__ __forceinline__ ull add2(ull a, ull b) {
    ull d; asm("add.rn.f32x2 %0, %1, %2;" : "=l"(d) : "l"(a), "l"(b)); return d;
}
__device__ __forceinline__ ull pack2(float lo, float hi) {
    ull d; asm("mov.b64 %0, {%1, %2};" : "=l"(d) : "f"(lo), "f"(hi)); return d;
}
__device__ __forceinline__ float2 unpack2(ull v) {
    float2 r; asm("mov.b64 {%0, %1}, %2;" : "=f"(r.x), "=f"(r.y) : "l"(v)); return r;
}
__device__ __forceinline__ float hsum2(ull v) {
    float2 r = unpack2(v); return r.x + r.y;
}

// ---------------------------------------------------------------------------
// Phase 1: a = tanh(lc1_w x + lc1_b);  gates = W_ih a + b_ih
// Stored per (row, i) as float4: ( 0.5*(xr_i + bhh_r_i),
//                                  0.5*(xz_i + bhh_z_i),
//                                  xn_i,  0 )
// W_ih rows 0..47 pre-scaled by 0.5 at smem-load time so the r/z dots come
// out already halved. 2 rows per thread; x rows direct from global (LDG.64).
// ---------------------------------------------------------------------------
__global__ __launch_bounds__(128) void vad_phase1(
    const float* __restrict__ x, const float* __restrict__ lc1_w,
    const float* __restrict__ lc1_b, const float* __restrict__ w_ih,
    const float* __restrict__ b_ih, const float* __restrict__ b_hh)
{
    __shared__ __align__(16) float s_w1[HH * FINP];   // lc1_w padded stride 44
    __shared__ float s_b1[HH];
    __shared__ __align__(16) ull s_wi2[G3 * 12];      // w_ih rows (r/z pre-halved)
    __shared__ float s_cb[G3];                        // folded gate biases

    int tid = threadIdx.x;
    for (int i = tid; i < HH * FINP; i += 128) {
        int h = i / FINP, f = i - h * FINP;
        s_w1[i] = (f < FIN) ? lc1_w[h * FIN + f] : 0.0f;
    }
    const ull* wi8 = (const ull*)w_ih;
    for (int i = tid; i < G3 * 12; i += 128) {
        ull w = wi8[i];
        if (i < 48 * 12) {                 // rows 0..47 (r,z): scale by 0.5
            float2 f = unpack2(w);
            w = pack2(0.5f * f.x, 0.5f * f.y);
        }
        s_wi2[i] = w;
    }
    if (tid < G3) {
        float b = b_ih[tid];
        // r rows (0..23): 0.5*(b_ih + b_hh_r); z rows (24..47): same pattern;
        // n rows (48..71): plain b_ih (b_hh_n stays in phase2's accumulator).
        s_cb[tid] = (tid < 48) ? 0.5f * (b + b_hh[tid]) : b;
    }
    if (tid < HH) s_b1[tid] = lc1_b[tid];
    __syncthreads();

    size_t r0 = (size_t)blockIdx.x * 256;
    const ull* xA = (const ull*)(x + (r0 + tid) * FIN);
    const ull* xB = (const ull*)(x + (r0 + 128 + tid) * FIN);

    ull xpA[22], xpB[22];
#pragma unroll
    for (int q = 0; q < 21; q++) { xpA[q] = xA[q]; xpB[q] = xB[q]; }
    xpA[21] = 0ULL; xpB[21] = 0ULL;

    // lc1 + tanh for both rows
    float aA[HH], aB[HH];
#pragma unroll
    for (int h = 0; h < HH; h++) {
        const ulonglong2* wv = (const ulonglong2*)&s_w1[h * FINP];
        float b = s_b1[h];
        ull pA = pack2(b, 0.0f), qA = 0ULL, pB = pack2(b, 0.0f), qB = 0ULL;
#pragma unroll
        for (int m = 0; m < 11; m++) {
            ulonglong2 w = wv[m];
            pA = fma2(w.x, xpA[2 * m], pA);
            qA = fma2(w.y, xpA[2 * m + 1], qA);
            pB = fma2(w.x, xpB[2 * m], pB);
            qB = fma2(w.y, xpB[2 * m + 1], qB);
        }
        aA[h] = tanh_a(hsum2(add2(pA, qA)));
        aB[h] = tanh_a(hsum2(add2(pB, qB)));
    }

    ull a2A[12], a2B[12];
#pragma unroll
    for (int k = 0; k < 12; k++) {
        a2A[k] = pack2(aA[2 * k], aA[2 * k + 1]);
        a2B[k] = pack2(aB[2 * k], aB[2 * k + 1]);
    }

    // per i: gates (i, 24+i, 48+i) for both rows -> float4 store each
    float4* outA = (float4*)(g_xg2 + (r0 + tid) * HH * 4);
    float4* outB = (float4*)(g_xg2 + (r0 + 128 + tid) * HH * 4);
#pragma unroll
    for (int i = 0; i < HH; i++) {
        float oA[3], oB[3];
#pragma unroll
        for (int s = 0; s < 3; s++) {
            int g = s * HH + i;
            const ulonglong2* w2 = (const ulonglong2*)&s_wi2[g * 12];
            float b = s_cb[g];
            ull pA = pack2(b, 0.0f), qA = 0ULL, pB = pack2(b, 0.0f), qB = 0ULL;
#pragma unroll
            for (int m = 0; m < 6; m++) {
                ulonglong2 w = w2[m];
                pA = fma2(w.x, a2A[2 * m], pA);
                qA = fma2(w.y, a2A[2 * m + 1], qA);
                pB = fma2(w.x, a2B[2 * m], pB);
                qB = fma2(w.y, a2B[2 * m + 1], qB);
            }
            oA[s] = hsum2(add2(pA, qA));
            oB[s] = hsum2(add2(pB, qB));
        }
        outA[i] = make_float4(oA[0], oA[1], oA[2], 0.0f);
        outB[i] = make_float4(oB[0], oB[1], oB[2], 0.0f);
    }
}

// ---------------------------------------------------------------------------
// Phase 2: GRU recurrence. One warp per batch row; h[i] in lane i.
// Per step: 1 LDG.128 (prefetched U=8 ahead), smem h-broadcast, 36 fma2,
// 3 MUFU tanh. All biases/scales pre-folded by phase1.
// ---------------------------------------------------------------------------
__global__ __launch_bounds__(32) void vad_phase2(
    const float* __restrict__ w_hh, const float* __restrict__ b_hh)
{
    __shared__ __align__(16) float s_h[2][32];
    int lane = threadIdx.x;
    int b = blockIdx.x;
    int i = (lane < HH) ? lane : 0;

    const ull* w8 = (const ull*)w_hh;
    ull wr2[12], wz2[12], wn2[12];
#pragma unroll
    for (int k = 0; k < 12; k++) {
        float2 r = unpack2(w8[(0 * HH + i) * 12 + k]);
        wr2[k] = pack2(0.5f * r.x, 0.5f * r.y);
        float2 z = unpack2(w8[(1 * HH + i) * 12 + k]);
        wz2[k] = pack2(0.5f * z.x, 0.5f * z.y);
        wn2[k] = w8[(2 * HH + i) * 12 + k];
    }
    ull bn2 = pack2(b_hh[2 * HH + i], 0.0f);

    const float4* xgp = (const float4*)(g_xg2 + (size_t)b * TT * HH * 4) + i;
    float* hp = g_h + (size_t)b * TT * HH;

    float h = 0.0f;
    const int U = 8;   // TT % U == 0
    float4 cb[U];
#pragma unroll
    for (int u = 0; u < U; u++) cb[u] = xgp[u * HH];

    for (int t0 = 0; t0 < TT; t0 += U) {
        // prefetch next chunk (pure loads, off the serial chain)
        float4 nb[U];
        bool more = (t0 + U) < TT;
        const float4* np = xgp + (size_t)(t0 + U) * HH;
#pragma unroll
        for (int u = 0; u < U; u++)
            nb[u] = more ? np[u * HH] : make_float4(0.f, 0.f, 0.f, 0.f);

#pragma unroll
        for (int u = 0; u < U; u++) {
            int pb = u & 1;
            s_h[pb][lane] = h;
            __syncwarp();
            ull h2[12];
            {
                const ulonglong2* sh2 = (const ulonglong2*)&s_h[pb][0];
#pragma unroll
                for (int k = 0; k < 6; k++) {
                    ulonglong2 t = sh2[k];
                    h2[2 * k] = t.x; h2[2 * k + 1] = t.y;
                }
            }
            float4 c = cb[u];
            ull ra = pack2(c.x, 0.0f), rb = 0ULL;
            ull za = pack2(c.y, 0.0f), zb = 0ULL;
            ull na = bn2, nb2 = 0ULL;
#pragma unroll
            for (int m = 0; m < 6; m++) {
                ra  = fma2(wr2[2 * m],     h2[2 * m],     ra);
                rb  = fma2(wr2[2 * m + 1], h2[2 * m + 1], rb);
                za  = fma2(wz2[2 * m],     h2[2 * m],     za);
                zb  = fma2(wz2[2 * m + 1], h2[2 * m + 1], zb);
                na  = fma2(wn2[2 * m],     h2[2 * m],     na);
                nb2 = fma2(wn2[2 * m + 1], h2[2 * m + 1], nb2);
            }
            float hr = hsum2(add2(ra, rb));
            float hz = hsum2(add2(za, zb));
            float hn = hsum2(add2(na, nb2));

            float r = fmaf(tanh_a(hr), 0.5f, 0.5f);
            float z = fmaf(tanh_a(hz), 0.5f, 0.5f);
            float n = tanh_a(fmaf(r, hn, c.z));
            h = fmaf(z, h - n, n);

            if (lane < HH) hp[(t0 + u) * HH + lane] = h;
        }

#pragma unroll
        for (int u = 0; u < U; u++) cb[u] = nb[u];
    }
}

// ---------------------------------------------------------------------------
// Phase 3: out[b,t] = sigmoid(lc2_w . h[b,t,:] + lc2_b). One thread per row.
// ---------------------------------------------------------------------------
__global__ __launch_bounds__(256) void vad_phase3(
    const float* __restrict__ lc2_w, const float* __restrict__ lc2_b,
    float* __restrict__ out)
{
    size_t idx = (size_t)blockIdx.x * 256 + threadIdx.x;
    const float4* hv = (const float4*)(g_h + idx * HH);
    const float4* wv = (const float4*)lc2_w;

    ull acc = pack2(0.5f * lc2_b[0], 0.0f);
#pragma unroll
    for (int q = 0; q < 6; q++) {
        float4 hq = hv[q];
        float4 wq = __ldg(&wv[q]);
        acc = fma2(pack2(hq.x, hq.y), pack2(0.5f * wq.x, 0.5f * wq.y), acc);
        acc = fma2(pack2(hq.z, hq.w), pack2(0.5f * wq.z, 0.5f * wq.w), acc);
    }
    out[idx] = fmaf(tanh_a(hsum2(acc)), 0.5f, 0.5f);
}

extern "C" void kernel_launch(void* const* d_in, const int* in_sizes, int n_in,
                              void* d_out, int out_size) {
    const float* x     = (const float*)d_in[0];
    const float* lc1_w = (const float*)d_in[1];
    const float* lc1_b = (const float*)d_in[2];
    const float* w_ih  = (const float*)d_in[3];
    const float* w_hh  = (const float*)d_in[4];
    const float* b_ih  = (const float*)d_in[5];
    const float* b_hh  = (const float*)d_in[6];
    const float* lc2_w = (const float*)d_in[7];
    const float* lc2_b = (const float*)d_in[8];
    float* out = (float*)d_out;

    vad_phase1<<<ROWS / 256, 128>>>(x, lc1_w, lc1_b, w_ih, b_ih, b_hh);
    vad_phase2<<<BB, 32>>>(w_hh, b_hh);
    vad_phase3<<<ROWS / 256, 256>>>(lc2_w, lc2_b, out);
}